// round 14
// baseline (speedup 1.0000x reference)
#include <cuda_runtime.h>
#include <cuda_bf16.h>

#define N 8192
#define ROWLEN 85
#define NCLS 80
#define CAP 256
#define MW 8               // CAP/32 suppression-mask words
#define FT 1024            // threads per block
#define NBLK 144           // 80 NMS + 1 rank + 63 P1/P3 helpers; single wave
#define BINS 16384         // bin = (key>>16) - 0xC080  (scores in [0,1))
#define PFE 5              // prefetched output elements per thread

__device__ unsigned g_skey[N];          // ~float_bits(score); asc == score desc
__device__ unsigned g_pack[N];          // row<<7 | cat
__device__ unsigned g_hist[BINS];       // bin counts (reset in P3)
__device__ int g_rank[N];               // row -> global sorted position
__device__ float g_keepf[N];            // keep flag by original row
__device__ unsigned long long g_tick;   // monotone ticket counter (epochs)
__device__ unsigned long long g_c1;     // P1 done (144)
__device__ unsigned long long g_c2;     // P2 done (144)

struct NmsShared {
    unsigned long long keys[CAP];    // compacted (unsorted)
    unsigned long long skeys[CAP];   // counting-sorted
    float4 box[CAP];
    float area[CAP];
    unsigned mask[(CAP + 1) * MW];   // +1 row: merge prefetch overshoot
    unsigned sup[MW];
    int cnt;
};

struct RankShared {                  // 112 KB, single rank block only
    unsigned prefix[BINS];           // excl prefix -> end-pointers after scatter
    unsigned bkey[N];
    unsigned short brow[N];
};

// arrive + spin barrier on a monotone counter (replay-safe: epoch-scaled
// targets). Thread-0 fence after __syncthreads is sufficient: PTX fences are
// cumulative, covering all block writes that happen-before via the barrier.
__device__ __forceinline__ void gsync(unsigned long long* c, unsigned long long tgt) {
    __syncthreads();
    if (threadIdx.x == 0) {
        __threadfence();
        atomicAdd(c, 1ull);
        while (*(volatile unsigned long long*)c < tgt) {}
        __threadfence();
    }
    __syncthreads();
}

__global__ void __launch_bounds__(FT, 1)
yolonms_kernel(const float* __restrict__ X, float* __restrict__ out) {
    extern __shared__ __align__(16) char sm[];
    __shared__ unsigned long long s_ep;
    __shared__ unsigned s_ws[32];

    int t = threadIdx.x, b = blockIdx.x;
    int lane = t & 31, w = t >> 5;

    if (t == 0) s_ep = atomicAdd(&g_tick, 1ull) / NBLK;
    __syncthreads();
    unsigned long long ep = s_ep;

    // ---------------- Phase 1: score + histogram (all blocks) ----------------
    for (int r = b * 32 + w; r < N; r += NBLK * 32) {
        const float* row = X + (long)r * ROWLEN;
        float v0 = row[5 + lane];
        float v1 = row[37 + lane];
        float v2 = (lane < 16) ? row[69 + lane] : -1.0f;
        float best = v0; int bi = lane;
        if (v1 > best) { best = v1; bi = lane + 32; }
        if (v2 > best) { best = v2; bi = lane + 64; }

        unsigned bb = __float_as_uint(best);            // nonneg -> monotone
        unsigned vmax = __reduce_max_sync(0xffffffffu, bb);
        int cand = (bb == vmax) ? bi : 0x7fffffff;      // smallest idx wins ties
        int bimin = __reduce_min_sync(0xffffffffu, cand);
        if (lane == 0) {
            float score = row[4] * __uint_as_float(vmax);   // in [0, 1)
            unsigned key = ~__float_as_uint(score);
            g_skey[r] = key;
            g_pack[r] = ((unsigned)r << 7) | (unsigned)bimin;
            unsigned bin = (key >> 16) - 0xC080u;
            if (bin >= BINS) bin = BINS - 1;
            atomicAdd(&g_hist[bin], 1u);
        }
    }
    gsync(&g_c1, (ep + 1) * NBLK);

    // ---------------- Phase 2: NMS blocks || single rank block ----------------
    if (b < NCLS) {
        // per-class greedy NMS. Class offsets in the reference make cross-
        // class IoU exactly 0, so suppression decomposes per class.
        NmsShared& S = *reinterpret_cast<NmsShared*>(sm);
        unsigned c = b;

        if (t == 0) S.cnt = 0;
        __syncthreads();

        // front-load pack+key values (one MLP burst), compact from registers
        unsigned pk[N / FT], sk[N / FT];
        #pragma unroll
        for (int q = 0; q < N / FT; q++) {
            pk[q] = g_pack[q * FT + t];
            sk[q] = g_skey[q * FT + t];
        }
        #pragma unroll
        for (int q = 0; q < N / FT; q++) {
            if ((pk[q] & 127u) == c) {
                int slot = atomicAdd(&S.cnt, 1);
                if (slot < CAP)
                    S.keys[slot] = ((unsigned long long)sk[q] << 32) | pk[q];
            }
        }
        __syncthreads();
        int m = min(S.cnt, CAP);

        // counting sort: keys unique (row embedded) -> exact stable order
        if (t < m) {
            unsigned long long k = S.keys[t];
            int r = 0;
            for (int j = 0; j < m; j++) r += (S.keys[j] < k);
            S.skeys[r] = k;
        }
        __syncthreads();

        if (t < m) {
            int idx = (int)(((unsigned)(S.skeys[t] & 0xFFFFFFFFull)) >> 7);
            const float* row = X + (long)idx * ROWLEN;
            float x1 = row[0], y1 = row[1], x2 = row[2], y2 = row[3];
            S.box[t] = make_float4(x1, y1, x2, y2);
            S.area[t] = (x2 - x1) * (y2 - y1);
        }
        for (int p = t; p < (m + 1) * MW; p += FT) S.mask[p] = 0u;
        __syncthreads();

        // mask[i] = { j > i : IoU(i,j) > 0.5 } — fully parallel over 32 warps
        for (int i = w; i < m; i += FT / 32) {
            float4 bi = S.box[i];
            float ai = S.area[i];
            for (int j = i + 1 + lane; j < m; j += 32) {
                float4 bj = S.box[j];
                float xx1 = fmaxf(bi.x, bj.x);
                float yy1 = fmaxf(bi.y, bj.y);
                float xx2 = fminf(bi.z, bj.z);
                float yy2 = fminf(bi.w, bj.w);
                float ww = fmaxf(xx2 - xx1, 0.0f);
                float hh = fmaxf(yy2 - yy1, 0.0f);
                float inter = ww * hh;
                float iou = inter / (ai + S.area[j] - inter);
                if (iou > 0.5f) atomicOr(&S.mask[i * MW + (j >> 5)], 1u << (j & 31));
            }
        }
        __syncthreads();

        // serial greedy bit-merge, single thread, unconditional prefetch
        if (t == 0) {
            unsigned sx[MW];
            #pragma unroll
            for (int q = 0; q < MW; q++) sx[q] = 0u;
            unsigned pm[MW];
            #pragma unroll
            for (int q = 0; q < MW; q++) pm[q] = S.mask[q];
            for (int i = 0; i < m; i++) {
                unsigned nm[MW];
                #pragma unroll
                for (int q = 0; q < MW; q++) nm[q] = S.mask[(i + 1) * MW + q];
                unsigned kept = ((sx[i >> 5] >> (i & 31)) & 1u) ^ 1u;
                unsigned sel = 0u - kept;          // all-ones if kept
                #pragma unroll
                for (int q = 0; q < MW; q++) sx[q] |= (pm[q] & sel);
                #pragma unroll
                for (int q = 0; q < MW; q++) pm[q] = nm[q];
            }
            #pragma unroll
            for (int q = 0; q < MW; q++) S.sup[q] = sx[q];
        }
        __syncthreads();

        if (t < m) {
            int idx = (int)(((unsigned)(S.skeys[t] & 0xFFFFFFFFull)) >> 7);
            g_keepf[idx] = ((S.sup[t >> 5] >> (t & 31)) & 1u) ? 0.0f : 1.0f;
        }
    } else if (b == NCLS) {
        // ---- single-block counting-rank: no global barriers inside ----
        RankShared& R = *reinterpret_cast<RankShared*>(sm);

        // load 16 bins/thread, local sums, block-scan of 1024 partials
        unsigned h[BINS / FT];
        unsigned tsum = 0;
        int base = t * (BINS / FT);
        #pragma unroll
        for (int l = 0; l < BINS / FT; l++) { h[l] = g_hist[base + l]; tsum += h[l]; }

        unsigned incl = tsum;
        #pragma unroll
        for (int off = 1; off < 32; off <<= 1) {
            unsigned u = __shfl_up_sync(0xffffffffu, incl, off);
            if (lane >= off) incl += u;
        }
        if (lane == 31) s_ws[w] = incl;
        __syncthreads();
        if (t < 32) {
            unsigned x = s_ws[lane];
            #pragma unroll
            for (int off = 1; off < 32; off <<= 1) {
                unsigned u = __shfl_up_sync(0xffffffffu, x, off);
                if (lane >= off) x += u;
            }
            s_ws[lane] = x;                      // inclusive warp-total scan
        }
        __syncthreads();
        unsigned run = ((w > 0) ? s_ws[w - 1] : 0u) + incl - tsum;  // excl base
        #pragma unroll
        for (int l = 0; l < BINS / FT; l++) { R.prefix[base + l] = run; run += h[l]; }
        __syncthreads();

        // scatter: smem atomics turn prefix[] into end-pointers
        #pragma unroll
        for (int k = 0; k < N / FT; k++) {
            int r = k * FT + t;
            unsigned key = g_skey[r];
            unsigned bin = (key >> 16) - 0xC080u;
            if (bin >= BINS) bin = BINS - 1;
            unsigned slot = atomicAdd(&R.prefix[bin], 1u);
            R.bkey[slot] = key;
            R.brow[slot] = (unsigned short)r;
        }
        __syncthreads();

        // exact rank: start(bin) = prefix[bin-1] (post-scatter), tie by row asc
        #pragma unroll
        for (int k = 0; k < N / FT; k++) {
            int s = k * FT + t;
            unsigned key = R.bkey[s];
            int row = (int)R.brow[s];
            unsigned bin = (key >> 16) - 0xC080u;
            if (bin >= BINS) bin = BINS - 1;
            unsigned start = (bin == 0) ? 0u : R.prefix[bin - 1];
            unsigned end = R.prefix[bin];
            int cnt = 0;
            for (unsigned i = start; i < end; i++) {
                unsigned k2 = R.bkey[i];
                if (k2 < key || (k2 == key && (int)R.brow[i] < row)) cnt++;
            }
            g_rank[row] = (int)start + cnt;
        }
    }
    // blocks 81..143: idle through P2, rejoin for P3

    // ---- prefetch P3's X values (X is read-only input; safe to issue early;
    // latency hides behind the barrier wait) ----
    const int total = N * ROWLEN;
    float xv[PFE];
    #pragma unroll
    for (int k = 0; k < PFE; k++) {
        int e = b * FT + t + k * NBLK * FT;
        xv[k] = (e < total) ? X[e] : 0.0f;
    }

    gsync(&g_c2, (ep + 1) * NBLK);

    // ---------------- Phase 3: output scatter + reset for next epoch ----------------
    // Plain loads (no __ldg): g_rank/g_keepf are kernel-mutated; ld.global.nc
    // would license hoisting across the barrier.
    for (int i = b * FT + t; i < BINS; i += NBLK * FT) g_hist[i] = 0u;
    #pragma unroll
    for (int k = 0; k < PFE; k++) {
        int e = b * FT + t + k * NBLK * FT;
        if (e < total) {
            int row = e / ROWLEN;
            int col = e - row * ROWLEN;
            int rk = g_rank[row];
            float kf = g_keepf[row];
            out[(long)rk * ROWLEN + col] = xv[k] * kf;
        }
    }
}

// ---------------------------------------------------------------------------
extern "C" void kernel_launch(void* const* d_in, const int* in_sizes, int n_in,
                              void* d_out, int out_size) {
    const float* X = (const float*)d_in[0];
    float* out = (float*)d_out;

    int nms_bytes = (int)sizeof(NmsShared);
    int rank_bytes = (int)sizeof(RankShared);
    int smem = nms_bytes > rank_bytes ? nms_bytes : rank_bytes;

    static int smem_set = 0;
    if (!smem_set) {
        cudaFuncSetAttribute(yolonms_kernel,
                             cudaFuncAttributeMaxDynamicSharedMemorySize, smem);
        smem_set = 1;
    }

    yolonms_kernel<<<NBLK, FT, smem>>>(X, out);
}

// round 15
// speedup vs baseline: 1.3485x; 1.3485x over previous
#include <cuda_runtime.h>
#include <cuda_bf16.h>

#define N 8192
#define ROWLEN 85
#define NCLS 80
#define CAP 256
#define MW 8               // CAP/32 suppression-mask words
#define FT 1024            // threads per block
#define NBLK 144           // 80 NMS + 64 rank; single wave, 1 block/SM
#define RB 64              // rank blocks (ids 80..143)
#define BINS 16384         // bin = (key>>16) - 0xC080  (scores in [0,1))
#define ROWS_PER_RB (N / RB)   // 128
#define PFE 5              // prefetched output elements per thread

__device__ unsigned g_skey[N];          // ~float_bits(score); asc == score desc
__device__ unsigned g_pack[N];          // row<<7 | cat
__device__ unsigned g_hist[BINS];       // bin counts (reset in P3)
__device__ unsigned g_cnt2[BINS];       // scatter cursors (reset in P3)
__device__ unsigned g_bkey[N];          // bucketed keys
__device__ int g_brow[N];               // bucketed rows
__device__ int g_rank[N];               // row -> global sorted position
__device__ float g_keepf[N];            // keep flag by original row
__device__ unsigned long long g_tick;   // monotone ticket counter (epochs)
__device__ unsigned long long g_c1;     // P1 done (144)
__device__ unsigned long long g_r3;     // scatter done (64 rank blocks)
__device__ unsigned long long g_c2;     // P2 done (144)

struct NmsShared {
    unsigned long long keys[CAP];    // compacted (unsorted)
    unsigned long long skeys[CAP];   // counting-sorted
    float4 box[CAP];
    float area[CAP];
    unsigned mask[(CAP + 1) * MW];   // +1 row: merge prefetch overshoot
    unsigned sup[MW];
    int cnt;
};

struct RankShared {                  // per-rank-block local copy of the prefix
    unsigned prefix[BINS];           // exclusive bin prefix (64 KB)
};

// arrive + spin barrier on a monotone counter (replay-safe: epoch-scaled
// targets). Thread-0 fence after __syncthreads is sufficient (cumulativity).
__device__ __forceinline__ void gsync(unsigned long long* c, unsigned long long tgt) {
    __syncthreads();
    if (threadIdx.x == 0) {
        __threadfence();
        atomicAdd(c, 1ull);
        while (*(volatile unsigned long long*)c < tgt) {}
        __threadfence();
    }
    __syncthreads();
}

__global__ void __launch_bounds__(FT, 1)
yolonms_kernel(const float* __restrict__ X, float* __restrict__ out) {
    extern __shared__ __align__(16) char sm[];
    __shared__ unsigned long long s_ep;
    __shared__ unsigned s_ws[32];

    int t = threadIdx.x, b = blockIdx.x;
    int lane = t & 31, w = t >> 5;

    if (t == 0) s_ep = atomicAdd(&g_tick, 1ull) / NBLK;
    __syncthreads();
    unsigned long long ep = s_ep;

    // ---------------- Phase 1: score + histogram (all blocks) ----------------
    // Explicit 2-iteration unroll: both row-load bursts issue before either
    // reduction (MLP=6 instead of a serial load->reduce->load chain).
    {
        int r0 = b * 32 + w;
        int r1 = r0 + NBLK * 32;
        float a0 = -1.f, a1 = -1.f, a2 = -1.f, b0 = -1.f, b1 = -1.f, b2 = -1.f;
        float o0 = 0.f, o1 = 0.f;
        if (r0 < N) {
            const float* row = X + (long)r0 * ROWLEN;
            a0 = row[5 + lane]; a1 = row[37 + lane];
            a2 = (lane < 16) ? row[69 + lane] : -1.0f;
            o0 = row[4];
        }
        if (r1 < N) {
            const float* row = X + (long)r1 * ROWLEN;
            b0 = row[5 + lane]; b1 = row[37 + lane];
            b2 = (lane < 16) ? row[69 + lane] : -1.0f;
            o1 = row[4];
        }
        #pragma unroll
        for (int it = 0; it < 2; it++) {
            int r = it ? r1 : r0;
            if (r >= N) continue;
            float v0 = it ? b0 : a0, v1 = it ? b1 : a1, v2 = it ? b2 : a2;
            float obj = it ? o1 : o0;
            float best = v0; int bi = lane;
            if (v1 > best) { best = v1; bi = lane + 32; }
            if (v2 > best) { best = v2; bi = lane + 64; }
            unsigned bb = __float_as_uint(best);            // nonneg -> monotone
            unsigned vmax = __reduce_max_sync(0xffffffffu, bb);
            int cand = (bb == vmax) ? bi : 0x7fffffff;      // smallest idx wins ties
            int bimin = __reduce_min_sync(0xffffffffu, cand);
            if (lane == 0) {
                float score = obj * __uint_as_float(vmax);  // in [0, 1)
                unsigned key = ~__float_as_uint(score);
                g_skey[r] = key;
                g_pack[r] = ((unsigned)r << 7) | (unsigned)bimin;
                unsigned bin = (key >> 16) - 0xC080u;
                if (bin >= BINS) bin = BINS - 1;
                atomicAdd(&g_hist[bin], 1u);
            }
        }
    }
    gsync(&g_c1, (ep + 1) * NBLK);

    // ---------------- Phase 2: NMS blocks || rank blocks ----------------
    if (b < NCLS) {
        // per-class greedy NMS. Class offsets in the reference make cross-
        // class IoU exactly 0, so suppression decomposes per class.
        NmsShared& S = *reinterpret_cast<NmsShared*>(sm);
        unsigned c = b;

        if (t == 0) S.cnt = 0;
        __syncthreads();

        unsigned pk[N / FT], sk[N / FT];
        #pragma unroll
        for (int q = 0; q < N / FT; q++) {
            pk[q] = g_pack[q * FT + t];
            sk[q] = g_skey[q * FT + t];
        }
        #pragma unroll
        for (int q = 0; q < N / FT; q++) {
            if ((pk[q] & 127u) == c) {
                int slot = atomicAdd(&S.cnt, 1);
                if (slot < CAP)
                    S.keys[slot] = ((unsigned long long)sk[q] << 32) | pk[q];
            }
        }
        __syncthreads();
        int m = min(S.cnt, CAP);

        // counting sort: keys unique (row embedded) -> exact stable order
        if (t < m) {
            unsigned long long k = S.keys[t];
            int r = 0;
            for (int j = 0; j < m; j++) r += (S.keys[j] < k);
            S.skeys[r] = k;
        }
        __syncthreads();

        if (t < m) {
            int idx = (int)(((unsigned)(S.skeys[t] & 0xFFFFFFFFull)) >> 7);
            const float* row = X + (long)idx * ROWLEN;
            float x1 = row[0], y1 = row[1], x2 = row[2], y2 = row[3];
            S.box[t] = make_float4(x1, y1, x2, y2);
            S.area[t] = (x2 - x1) * (y2 - y1);
        }
        for (int p = t; p < (m + 1) * MW; p += FT) S.mask[p] = 0u;
        __syncthreads();

        for (int i = w; i < m; i += FT / 32) {
            float4 bi = S.box[i];
            float ai = S.area[i];
            for (int j = i + 1 + lane; j < m; j += 32) {
                float4 bj = S.box[j];
                float xx1 = fmaxf(bi.x, bj.x);
                float yy1 = fmaxf(bi.y, bj.y);
                float xx2 = fminf(bi.z, bj.z);
                float yy2 = fminf(bi.w, bj.w);
                float ww = fmaxf(xx2 - xx1, 0.0f);
                float hh = fmaxf(yy2 - yy1, 0.0f);
                float inter = ww * hh;
                float iou = inter / (ai + S.area[j] - inter);
                if (iou > 0.5f) atomicOr(&S.mask[i * MW + (j >> 5)], 1u << (j & 31));
            }
        }
        __syncthreads();

        if (t == 0) {   // serial greedy bit-merge with unconditional prefetch
            unsigned sx[MW], pm[MW];
            #pragma unroll
            for (int q = 0; q < MW; q++) { sx[q] = 0u; pm[q] = S.mask[q]; }
            for (int i = 0; i < m; i++) {
                unsigned nm[MW];
                #pragma unroll
                for (int q = 0; q < MW; q++) nm[q] = S.mask[(i + 1) * MW + q];
                unsigned kept = ((sx[i >> 5] >> (i & 31)) & 1u) ^ 1u;
                unsigned sel = 0u - kept;
                #pragma unroll
                for (int q = 0; q < MW; q++) sx[q] |= (pm[q] & sel);
                #pragma unroll
                for (int q = 0; q < MW; q++) pm[q] = nm[q];
            }
            #pragma unroll
            for (int q = 0; q < MW; q++) S.sup[q] = sx[q];
        }
        __syncthreads();

        if (t < m) {
            int idx = (int)(((unsigned)(S.skeys[t] & 0xFFFFFFFFull)) >> 7);
            g_keepf[idx] = ((S.sup[t >> 5] >> (t & 31)) & 1u) ? 0.0f : 1.0f;
        }
    } else {
        // ---- rank blocks: each duplicates the full bin scan locally, so no
        // cross-block prefix exchange is needed (kills 2 barrier rounds). ----
        int rb = b - NCLS;
        RankShared& R = *reinterpret_cast<RankShared*>(sm);

        // local exclusive prefix of all 16K bins (block scan, 16 bins/thread)
        unsigned h[BINS / FT];
        unsigned tsum = 0;
        int base = t * (BINS / FT);
        #pragma unroll
        for (int l = 0; l < BINS / FT; l++) { h[l] = g_hist[base + l]; tsum += h[l]; }
        unsigned incl = tsum;
        #pragma unroll
        for (int off = 1; off < 32; off <<= 1) {
            unsigned u = __shfl_up_sync(0xffffffffu, incl, off);
            if (lane >= off) incl += u;
        }
        if (lane == 31) s_ws[w] = incl;
        __syncthreads();
        if (t < 32) {
            unsigned x = s_ws[lane];
            #pragma unroll
            for (int off = 1; off < 32; off <<= 1) {
                unsigned u = __shfl_up_sync(0xffffffffu, x, off);
                if (lane >= off) x += u;
            }
            s_ws[lane] = x;
        }
        __syncthreads();
        unsigned run = ((w > 0) ? s_ws[w - 1] : 0u) + incl - tsum;
        #pragma unroll
        for (int l = 0; l < BINS / FT; l++) { R.prefix[base + l] = run; run += h[l]; }
        __syncthreads();

        // scatter own 128 rows using local prefix + GLOBAL cursors
        if (t < ROWS_PER_RB) {
            int r = rb * ROWS_PER_RB + t;
            unsigned key = g_skey[r];
            unsigned bin = (key >> 16) - 0xC080u;
            if (bin >= BINS) bin = BINS - 1;
            unsigned slot = R.prefix[bin] + atomicAdd(&g_cnt2[bin], 1u);
            g_bkey[slot] = key;
            g_brow[slot] = r;
        }
        gsync(&g_r3, (ep + 1) * RB);

        // step D: warp-per-element within-bucket rank (parallel bucket scan).
        // 2048 warps total; each handles 4 elements.
        int g = rb * 32 + w;
        #pragma unroll
        for (int k = 0; k < 4; k++) {
            int s = g * 4 + k;
            unsigned key = g_bkey[s];
            int row = g_brow[s];
            unsigned bin = (key >> 16) - 0xC080u;
            if (bin >= BINS) bin = BINS - 1;
            unsigned start = R.prefix[bin];
            unsigned end = (bin + 1 < BINS) ? R.prefix[bin + 1] : (unsigned)N;
            unsigned len = end - start;
            int cnt = 0;
            for (unsigned bs = 0; bs < len; bs += 32) {
                unsigned i = bs + lane;
                bool pred = false;
                if (i < len) {
                    unsigned k2 = g_bkey[start + i];
                    int r2 = g_brow[start + i];
                    pred = (k2 < key) || (k2 == key && r2 < row);
                }
                cnt += __popc(__ballot_sync(0xffffffffu, pred));
            }
            if (lane == 0) g_rank[row] = (int)start + cnt;
        }
    }

    // ---- prefetch P3's X values (X is read-only input; safe to issue early;
    // latency hides behind the barrier wait) ----
    const int total = N * ROWLEN;
    float xv[PFE];
    #pragma unroll
    for (int k = 0; k < PFE; k++) {
        int e = b * FT + t + k * NBLK * FT;
        xv[k] = (e < total) ? X[e] : 0.0f;
    }

    gsync(&g_c2, (ep + 1) * NBLK);

    // ---------------- Phase 3: output scatter + reset for next epoch ----------------
    // Plain loads (no __ldg): g_rank/g_keepf are kernel-mutated.
    {
        int i = b * FT + t;
        if (i < BINS) { g_hist[i] = 0u; g_cnt2[i] = 0u; }
    }
    #pragma unroll
    for (int k = 0; k < PFE; k++) {
        int e = b * FT + t + k * NBLK * FT;
        if (e < total) {
            int row = e / ROWLEN;
            int col = e - row * ROWLEN;
            int rk = g_rank[row];
            float kf = g_keepf[row];
            out[(long)rk * ROWLEN + col] = xv[k] * kf;
        }
    }
}

// ---------------------------------------------------------------------------
extern "C" void kernel_launch(void* const* d_in, const int* in_sizes, int n_in,
                              void* d_out, int out_size) {
    const float* X = (const float*)d_in[0];
    float* out = (float*)d_out;

    int nms_bytes = (int)sizeof(NmsShared);
    int rank_bytes = (int)sizeof(RankShared);
    int smem = nms_bytes > rank_bytes ? nms_bytes : rank_bytes;

    static int smem_set = 0;
    if (!smem_set) {
        cudaFuncSetAttribute(yolonms_kernel,
                             cudaFuncAttributeMaxDynamicSharedMemorySize, smem);
        smem_set = 1;
    }

    yolonms_kernel<<<NBLK, FT, smem>>>(X, out);
}

// round 16
// speedup vs baseline: 1.4725x; 1.0920x over previous
#include <cuda_runtime.h>
#include <cuda_bf16.h>

#define N 8192
#define ROWLEN 85
#define NCLS 80
#define CAP 256
#define MW 8               // CAP/32 suppression-mask words
#define FT 1024            // threads per block
#define NBLK 144           // 80 NMS + 64 rank; single wave, 1 block/SM
#define RB 64              // rank blocks (ids 80..143)
#define BINS 16384         // bin = (key>>16) - 0xC080  (scores in [0,1))
#define ROWS_PER_RB (N / RB)   // 128

__device__ unsigned g_skey[N];          // ~float_bits(score); asc == score desc
__device__ unsigned g_pack[N];          // row<<7 | cat
__device__ unsigned g_hist[BINS];       // bin counts (reset at end)
__device__ unsigned g_cnt2[BINS];       // scatter cursors (reset at end)
__device__ unsigned g_bkey[N];          // bucketed keys
__device__ int g_brow[N];               // bucketed rows
__device__ int g_rank[N];               // row -> global sorted position
__device__ unsigned long long g_tick;   // monotone ticket counter (epochs)
__device__ unsigned long long g_c1;     // P1 done (144)
__device__ unsigned long long g_r3;     // bucket scatter done (64 rank blocks)
__device__ unsigned long long g_c2;     // P2 done (144)

struct NmsShared {
    unsigned long long keys[CAP];    // compacted (unsorted)
    unsigned long long skeys[CAP];   // counting-sorted (persists across B2)
    float4 box[CAP];
    float area[CAP];
    unsigned mask[(CAP + 1) * MW];   // +1 row: merge prefetch overshoot
    unsigned sup[MW];                // suppression bits (persists across B2)
    int cnt;
};

struct RankShared {
    unsigned prefix[BINS];           // per-block local exclusive bin prefix
};

// arrive + spin barrier on a monotone counter (replay-safe: epoch-scaled
// targets). Thread-0 fence after __syncthreads suffices (fence cumulativity).
__device__ __forceinline__ void gsync(unsigned long long* c, unsigned long long tgt) {
    __syncthreads();
    if (threadIdx.x == 0) {
        __threadfence();
        atomicAdd(c, 1ull);
        while (*(volatile unsigned long long*)c < tgt) {}
        __threadfence();
    }
    __syncthreads();
}

__global__ void __launch_bounds__(FT, 1)
yolonms_kernel(const float* __restrict__ X, float* __restrict__ out) {
    extern __shared__ __align__(16) char sm[];
    __shared__ unsigned long long s_ep;
    __shared__ unsigned s_ws[32];

    int t = threadIdx.x, b = blockIdx.x;
    int lane = t & 31, w = t >> 5;

    if (t == 0) s_ep = atomicAdd(&g_tick, 1ull) / NBLK;
    __syncthreads();
    unsigned long long ep = s_ep;

    // ---------------- Phase 1: score + histogram (all blocks) ----------------
    {
        int r0 = b * 32 + w;
        int r1 = r0 + NBLK * 32;
        float a0 = -1.f, a1 = -1.f, a2 = -1.f, c0 = -1.f, c1 = -1.f, c2 = -1.f;
        float o0 = 0.f, o1 = 0.f;
        if (r0 < N) {
            const float* row = X + (long)r0 * ROWLEN;
            a0 = row[5 + lane]; a1 = row[37 + lane];
            a2 = (lane < 16) ? row[69 + lane] : -1.0f;
            o0 = row[4];
        }
        if (r1 < N) {
            const float* row = X + (long)r1 * ROWLEN;
            c0 = row[5 + lane]; c1 = row[37 + lane];
            c2 = (lane < 16) ? row[69 + lane] : -1.0f;
            o1 = row[4];
        }
        #pragma unroll
        for (int it = 0; it < 2; it++) {
            int r = it ? r1 : r0;
            if (r >= N) continue;
            float v0 = it ? c0 : a0, v1 = it ? c1 : a1, v2 = it ? c2 : a2;
            float obj = it ? o1 : o0;
            float best = v0; int bi = lane;
            if (v1 > best) { best = v1; bi = lane + 32; }
            if (v2 > best) { best = v2; bi = lane + 64; }
            unsigned bb = __float_as_uint(best);            // nonneg -> monotone
            unsigned vmax = __reduce_max_sync(0xffffffffu, bb);
            int cand = (bb == vmax) ? bi : 0x7fffffff;      // smallest idx wins ties
            int bimin = __reduce_min_sync(0xffffffffu, cand);
            if (lane == 0) {
                float score = obj * __uint_as_float(vmax);  // in [0, 1)
                unsigned key = ~__float_as_uint(score);
                g_skey[r] = key;
                g_pack[r] = ((unsigned)r << 7) | (unsigned)bimin;
                unsigned bin = (key >> 16) - 0xC080u;
                if (bin >= BINS) bin = BINS - 1;
                atomicAdd(&g_hist[bin], 1u);
            }
        }
    }
    gsync(&g_c1, (ep + 1) * NBLK);

    // ---------------- Phase 2: NMS blocks || rank blocks (rank also copies) ----
    int m = 0;   // NMS class size, persists to P3
    if (b < NCLS) {
        // per-class greedy NMS. Class offsets in the reference make cross-
        // class IoU exactly 0, so suppression decomposes per class.
        NmsShared& S = *reinterpret_cast<NmsShared*>(sm);
        unsigned c = b;

        if (t == 0) S.cnt = 0;
        __syncthreads();

        unsigned pk[N / FT], sk[N / FT];
        #pragma unroll
        for (int q = 0; q < N / FT; q++) {
            pk[q] = g_pack[q * FT + t];
            sk[q] = g_skey[q * FT + t];
        }
        #pragma unroll
        for (int q = 0; q < N / FT; q++) {
            if ((pk[q] & 127u) == c) {
                int slot = atomicAdd(&S.cnt, 1);
                if (slot < CAP)
                    S.keys[slot] = ((unsigned long long)sk[q] << 32) | pk[q];
            }
        }
        __syncthreads();
        m = min(S.cnt, CAP);

        // counting sort: keys unique (row embedded) -> exact stable order
        if (t < m) {
            unsigned long long k = S.keys[t];
            int r = 0;
            for (int j = 0; j < m; j++) r += (S.keys[j] < k);
            S.skeys[r] = k;
        }
        __syncthreads();

        if (t < m) {
            int idx = (int)(((unsigned)(S.skeys[t] & 0xFFFFFFFFull)) >> 7);
            const float* row = X + (long)idx * ROWLEN;
            float x1 = row[0], y1 = row[1], x2 = row[2], y2 = row[3];
            S.box[t] = make_float4(x1, y1, x2, y2);
            S.area[t] = (x2 - x1) * (y2 - y1);
        }
        for (int p = t; p < (m + 1) * MW; p += FT) S.mask[p] = 0u;
        __syncthreads();

        // mask[i] = { j > i : IoU(i,j) > 0.5 } — parallel over 32 warps
        for (int i = w; i < m; i += FT / 32) {
            float4 bi = S.box[i];
            float ai = S.area[i];
            for (int j = i + 1 + lane; j < m; j += 32) {
                float4 bj = S.box[j];
                float xx1 = fmaxf(bi.x, bj.x);
                float yy1 = fmaxf(bi.y, bj.y);
                float xx2 = fminf(bi.z, bj.z);
                float yy2 = fminf(bi.w, bj.w);
                float ww = fmaxf(xx2 - xx1, 0.0f);
                float hh = fmaxf(yy2 - yy1, 0.0f);
                float inter = ww * hh;
                float iou = inter / (ai + S.area[j] - inter);
                if (iou > 0.5f) atomicOr(&S.mask[i * MW + (j >> 5)], 1u << (j & 31));
            }
        }
        __syncthreads();

        if (t == 0) {   // serial greedy bit-merge with unconditional prefetch
            unsigned sx[MW], pm[MW];
            #pragma unroll
            for (int q = 0; q < MW; q++) { sx[q] = 0u; pm[q] = S.mask[q]; }
            for (int i = 0; i < m; i++) {
                unsigned nm[MW];
                #pragma unroll
                for (int q = 0; q < MW; q++) nm[q] = S.mask[(i + 1) * MW + q];
                unsigned kept = ((sx[i >> 5] >> (i & 31)) & 1u) ^ 1u;
                unsigned sel = 0u - kept;
                #pragma unroll
                for (int q = 0; q < MW; q++) sx[q] |= (pm[q] & sel);
                #pragma unroll
                for (int q = 0; q < MW; q++) pm[q] = nm[q];
            }
            #pragma unroll
            for (int q = 0; q < MW; q++) S.sup[q] = sx[q];
        }
        __syncthreads();
        // S.skeys + S.sup stay live in smem for the P3 zeroing pass.
    } else {
        // ---- rank blocks: counting-rank + immediate output copy ----
        int rb = b - NCLS;
        RankShared& R = *reinterpret_cast<RankShared*>(sm);

        // local exclusive prefix of all 16K bins (duplicated per block: no
        // cross-block prefix exchange barrier needed)
        unsigned h[BINS / FT];
        unsigned tsum = 0;
        int base = t * (BINS / FT);
        #pragma unroll
        for (int l = 0; l < BINS / FT; l++) { h[l] = g_hist[base + l]; tsum += h[l]; }
        unsigned incl = tsum;
        #pragma unroll
        for (int off = 1; off < 32; off <<= 1) {
            unsigned u = __shfl_up_sync(0xffffffffu, incl, off);
            if (lane >= off) incl += u;
        }
        if (lane == 31) s_ws[w] = incl;
        __syncthreads();
        if (t < 32) {
            unsigned x = s_ws[lane];
            #pragma unroll
            for (int off = 1; off < 32; off <<= 1) {
                unsigned u = __shfl_up_sync(0xffffffffu, x, off);
                if (lane >= off) x += u;
            }
            s_ws[lane] = x;
        }
        __syncthreads();
        unsigned run = ((w > 0) ? s_ws[w - 1] : 0u) + incl - tsum;
        #pragma unroll
        for (int l = 0; l < BINS / FT; l++) { R.prefix[base + l] = run; run += h[l]; }
        __syncthreads();

        // scatter own 128 rows into buckets (local prefix + global cursors)
        if (t < ROWS_PER_RB) {
            int r = rb * ROWS_PER_RB + t;
            unsigned key = g_skey[r];
            unsigned bin = (key >> 16) - 0xC080u;
            if (bin >= BINS) bin = BINS - 1;
            unsigned slot = R.prefix[bin] + atomicAdd(&g_cnt2[bin], 1u);
            g_bkey[slot] = key;
            g_brow[slot] = r;
        }
        gsync(&g_r3, (ep + 1) * RB);

        // warp-per-slot: exact rank, then copy the row straight to out[rank].
        // (ranks form a permutation -> every out row written exactly once)
        int g = rb * 32 + w;
        #pragma unroll
        for (int k = 0; k < 4; k++) {
            int s = g * 4 + k;
            unsigned key = g_bkey[s];
            int row = g_brow[s];
            unsigned bin = (key >> 16) - 0xC080u;
            if (bin >= BINS) bin = BINS - 1;
            unsigned start = R.prefix[bin];
            unsigned end = (bin + 1 < BINS) ? R.prefix[bin + 1] : (unsigned)N;
            unsigned len = end - start;
            int cnt = 0;
            for (unsigned bs = 0; bs < len; bs += 32) {
                unsigned i = bs + lane;
                bool pred = false;
                if (i < len) {
                    unsigned k2 = g_bkey[start + i];
                    int r2 = g_brow[start + i];
                    pred = (k2 < key) || (k2 == key && r2 < row);
                }
                cnt += __popc(__ballot_sync(0xffffffffu, pred));
            }
            int rk = (int)start + cnt;              // uniform across the warp
            if (lane == 0) g_rank[row] = rk;
            const float* src = X + (long)row * ROWLEN;
            float* dst = out + (long)rk * ROWLEN;
            #pragma unroll
            for (int c2 = lane; c2 < ROWLEN; c2 += 32) dst[c2] = src[c2];
        }
    }

    gsync(&g_c2, (ep + 1) * NBLK);

    // ------ Phase 3 (tiny): NMS blocks zero suppressed rows; reset counters ------
    {
        int i = b * FT + t;
        if (i < BINS) { g_hist[i] = 0u; g_cnt2[i] = 0u; }
    }
    if (b < NCLS) {
        NmsShared& S = *reinterpret_cast<NmsShared*>(sm);
        for (int i = w; i < m; i += FT / 32) {          // warp per class entry
            if ((S.sup[i >> 5] >> (i & 31)) & 1u) {
                int idx = (int)(((unsigned)(S.skeys[i] & 0xFFFFFFFFull)) >> 7);
                int rk = g_rank[idx];                    // plain load, post-B2
                float* dst = out + (long)rk * ROWLEN;
                #pragma unroll
                for (int c2 = lane; c2 < ROWLEN; c2 += 32) dst[c2] = 0.0f;
            }
        }
    }
}

// ---------------------------------------------------------------------------
extern "C" void kernel_launch(void* const* d_in, const int* in_sizes, int n_in,
                              void* d_out, int out_size) {
    const float* X = (const float*)d_in[0];
    float* out = (float*)d_out;

    int nms_bytes = (int)sizeof(NmsShared);
    int rank_bytes = (int)sizeof(RankShared);
    int smem = nms_bytes > rank_bytes ? nms_bytes : rank_bytes;

    static int smem_set = 0;
    if (!smem_set) {
        cudaFuncSetAttribute(yolonms_kernel,
                             cudaFuncAttributeMaxDynamicSharedMemorySize, smem);
        smem_set = 1;
    }

    yolonms_kernel<<<NBLK, FT, smem>>>(X, out);
}